// round 16
// baseline (speedup 1.0000x reference)
#include <cuda_runtime.h>
#include <cuda_fp16.h>
#include <cuda_bf16.h>
#include <cstdint>

// Problem constants (fixed by the dataset)
#define N_NODES_MAX 50048
#define N_EDGES_MAX 800000
#define IN_FEATS    128
#define NUM_HEADS   4
#define OUT_FEATS   32
#define HD          (NUM_HEADS * OUT_FEATS)   // 128

#define SCAN_B 1024
#define MAX_BLOCKS ((N_NODES_MAX + SCAN_B - 1) / SCAN_B + 2)

// Scratch (static __device__ arrays; no allocation allowed)
// g_cnt is zero at load and re-zeroed by agg_kernel each call (no memset node).
__device__ __half2 g_fth[N_NODES_MAX * 64];   // projected features, fp16 rows
__device__ int     g_cnt[N_NODES_MAX];        // in-degree histogram
__device__ int     g_off[N_NODES_MAX];        // CSR row starts
__device__ int     g_cur[N_NODES_MAX];        // scatter cursors
__device__ int     g_bsum[MAX_BLOCKS];        // per-block sums for scan
__device__ int     g_csr_src[N_EDGES_MAX];    // src node per CSR slot

// ---------------------------------------------------------------------------
// K1: in-degree histogram (g_cnt arrives zeroed — agg_kernel re-arms it)
// ---------------------------------------------------------------------------
__global__ void hist_kernel(const int* __restrict__ dst, int E) {
    int i = blockIdx.x * blockDim.x + threadIdx.x;
    if (i < E) atomicAdd(&g_cnt[dst[i]], 1);
}

// ---------------------------------------------------------------------------
// K2a: per-block sums for the scan
// ---------------------------------------------------------------------------
__global__ void scan_phase1(int N) {
    int i = blockIdx.x * SCAN_B + threadIdx.x;
    int v = (i < N) ? g_cnt[i] : 0;
    #pragma unroll
    for (int o = 16; o > 0; o >>= 1) v += __shfl_xor_sync(0xffffffffu, v, o);
    __shared__ int wsum[32];
    int lane = threadIdx.x & 31, w = threadIdx.x >> 5;
    if (lane == 0) wsum[w] = v;
    __syncthreads();
    if (w == 0) {
        int x = wsum[lane];
        #pragma unroll
        for (int o = 16; o > 0; o >>= 1) x += __shfl_xor_sync(0xffffffffu, x, o);
        if (lane == 0) g_bsum[blockIdx.x] = x;
    }
}

// ---------------------------------------------------------------------------
// K2b: per-block scan with inter-block base folded in (warp 0 sums g_bsum).
// ---------------------------------------------------------------------------
__global__ void scan_phase3(int N) {
    __shared__ int base_off;
    int lane = threadIdx.x & 31, w = threadIdx.x >> 5;
    if (threadIdx.x < 32) {
        int acc = 0;
        for (int j = lane; j < (int)blockIdx.x; j += 32) acc += g_bsum[j];
        #pragma unroll
        for (int o = 16; o > 0; o >>= 1) acc += __shfl_xor_sync(0xffffffffu, acc, o);
        if (lane == 0) base_off = acc;
    }
    int i = blockIdx.x * SCAN_B + threadIdx.x;
    int v = (i < N) ? g_cnt[i] : 0;
    int x = v;
    #pragma unroll
    for (int o = 1; o < 32; o <<= 1) {
        int y = __shfl_up_sync(0xffffffffu, x, o);
        if (lane >= o) x += y;
    }
    __shared__ int woff[32];
    if (lane == 31) woff[w] = x;
    __syncthreads();
    if (w == 0) {
        int y = woff[lane];
        int z = y;
        #pragma unroll
        for (int o = 1; o < 32; o <<= 1) {
            int t2 = __shfl_up_sync(0xffffffffu, z, o);
            if (lane >= o) z += t2;
        }
        woff[lane] = z - y;
    }
    __syncthreads();
    int excl = (x - v) + woff[w] + base_off;
    if (i < N) { g_off[i] = excl; g_cur[i] = excl; }
}

// ---------------------------------------------------------------------------
// K3: scatter src ids into CSR slots
// ---------------------------------------------------------------------------
__global__ void scatter_kernel(const int* __restrict__ src,
                               const int* __restrict__ dst, int E) {
    int i = blockIdx.x * blockDim.x + threadIdx.x;
    if (i < E) {
        int pos = atomicAdd(&g_cur[dst[i]], 1);
        g_csr_src[pos] = src[i];
    }
}

// ---------------------------------------------------------------------------
// K4: projection GEMM — R8 exact compute shape (measured best; frozen).
// 128x128 tile, BK=16, 256 threads, occ 2, 8x8 microtile as f32x2 pairs.
// Epilogue writes ONLY the fp16 rows (g_fth) — agg reads src AND dst from
// the fp16 mirror, so the fp32 copy is dead weight (saves 25.6MB of STG).
// Runs on a forked stream, concurrent with the CSR build.
// ---------------------------------------------------------------------------
#define GM 128
#define GK 16
__global__ void __launch_bounds__(256, 2)
gemm_kernel(const float* __restrict__ feat,
            const float* __restrict__ W,
            int N) {
    __shared__ float As[GK][GM];    // feat tile, transposed: As[k][r]   8KB
    __shared__ float Bs[GK][HD];    // W tile, transposed:    Bs[k][o]   8KB

    const int tid = threadIdx.x;           // 0..255
    const int tx  = tid & 15;              // col group: cols tx*8..tx*8+7
    const int ty  = tid >> 4;              // row group: rows ty*8..ty*8+7
    const int row0 = blockIdx.x * GM;

    const int rA0 = (tid + 0)   >> 2, kq0 = (tid + 0)   & 3;
    const int rA1 = (tid + 256) >> 2, kq1 = (tid + 256) & 3;

    unsigned long long acc[8][4];   // 8 rows x 4 f32x2 pairs (= 8 cols)
    #pragma unroll
    for (int i = 0; i < 8; i++)
        #pragma unroll
        for (int j = 0; j < 4; j++) acc[i][j] = 0ULL;

    float4 fa0, fa1, fw0, fw1;
    {
        fa0 = make_float4(0.f, 0.f, 0.f, 0.f);
        fa1 = fa0;
        if (row0 + rA0 < N) fa0 = *(const float4*)&feat[(size_t)(row0 + rA0) * IN_FEATS + (kq0 << 2)];
        if (row0 + rA1 < N) fa1 = *(const float4*)&feat[(size_t)(row0 + rA1) * IN_FEATS + (kq1 << 2)];
        fw0 = *(const float4*)&W[(size_t)rA0 * IN_FEATS + (kq0 << 2)];
        fw1 = *(const float4*)&W[(size_t)rA1 * IN_FEATS + (kq1 << 2)];
    }

    #pragma unroll 1
    for (int kb = 0; kb < IN_FEATS / GK; kb++) {
        As[(kq0 << 2) + 0][rA0] = fa0.x; As[(kq0 << 2) + 1][rA0] = fa0.y;
        As[(kq0 << 2) + 2][rA0] = fa0.z; As[(kq0 << 2) + 3][rA0] = fa0.w;
        As[(kq1 << 2) + 0][rA1] = fa1.x; As[(kq1 << 2) + 1][rA1] = fa1.y;
        As[(kq1 << 2) + 2][rA1] = fa1.z; As[(kq1 << 2) + 3][rA1] = fa1.w;
        Bs[(kq0 << 2) + 0][rA0] = fw0.x; Bs[(kq0 << 2) + 1][rA0] = fw0.y;
        Bs[(kq0 << 2) + 2][rA0] = fw0.z; Bs[(kq0 << 2) + 3][rA0] = fw0.w;
        Bs[(kq1 << 2) + 0][rA1] = fw1.x; Bs[(kq1 << 2) + 1][rA1] = fw1.y;
        Bs[(kq1 << 2) + 2][rA1] = fw1.z; Bs[(kq1 << 2) + 3][rA1] = fw1.w;
        __syncthreads();

        if (kb + 1 < IN_FEATS / GK) {
            int kc = (kb + 1) * GK;
            fa0 = make_float4(0.f, 0.f, 0.f, 0.f);
            fa1 = fa0;
            if (row0 + rA0 < N) fa0 = *(const float4*)&feat[(size_t)(row0 + rA0) * IN_FEATS + kc + (kq0 << 2)];
            if (row0 + rA1 < N) fa1 = *(const float4*)&feat[(size_t)(row0 + rA1) * IN_FEATS + kc + (kq1 << 2)];
            fw0 = *(const float4*)&W[(size_t)rA0 * IN_FEATS + kc + (kq0 << 2)];
            fw1 = *(const float4*)&W[(size_t)rA1 * IN_FEATS + kc + (kq1 << 2)];
        }

        #pragma unroll
        for (int k = 0; k < GK; k++) {
            float4 a0 = *(const float4*)&As[k][(ty << 3) + 0];
            float4 a1 = *(const float4*)&As[k][(ty << 3) + 4];
            float4 b0 = *(const float4*)&Bs[k][(tx << 3) + 0];
            float4 b1 = *(const float4*)&Bs[k][(tx << 3) + 4];
            unsigned long long bp[4];
            asm("mov.b64 %0, {%1, %2};" : "=l"(bp[0]) : "f"(b0.x), "f"(b0.y));
            asm("mov.b64 %0, {%1, %2};" : "=l"(bp[1]) : "f"(b0.z), "f"(b0.w));
            asm("mov.b64 %0, {%1, %2};" : "=l"(bp[2]) : "f"(b1.x), "f"(b1.y));
            asm("mov.b64 %0, {%1, %2};" : "=l"(bp[3]) : "f"(b1.z), "f"(b1.w));
            float av[8] = {a0.x, a0.y, a0.z, a0.w, a1.x, a1.y, a1.z, a1.w};
            #pragma unroll
            for (int i = 0; i < 8; i++) {
                unsigned long long ap;
                asm("mov.b64 %0, {%1, %1};" : "=l"(ap) : "f"(av[i]));
                #pragma unroll
                for (int jp = 0; jp < 4; jp++)
                    asm("fma.rn.f32x2 %0, %1, %2, %0;"
                        : "+l"(acc[i][jp]) : "l"(ap), "l"(bp[jp]));
            }
        }
        __syncthreads();
    }

    // Epilogue: fp16 mirror only (one STG.128 per row-chunk).
    #pragma unroll
    for (int i = 0; i < 8; i++) {
        int r = row0 + (ty << 3) + i;
        if (r < N) {
            __half2 hh[4];
            #pragma unroll
            for (int jp = 0; jp < 4; jp++) {
                float2 f = *reinterpret_cast<float2*>(&acc[i][jp]);
                hh[jp] = __floats2half2_rn(f.x, f.y);
            }
            *(uint4*)&g_fth[(size_t)r * 64 + (tx << 2)] = *(uint4*)&hh[0];
        }
    }
}

// ---------------------------------------------------------------------------
// K5: atomic-free aggregation — R14 half-warp-per-edge (measured best shape).
// Lanes 0-15 take edge t, lanes 16-31 edge t+1; lane holds 8 features
// (one uint4 of the 256B fp16 row); per-head reduction = 2 shuffles.
// dst row now ALSO read from the fp16 mirror (single LDG.128 per lane).
// Lane 0 re-zeros g_cnt[node] (replaces the memset graph node).
// Max-subtraction skipped: mathematically identical softmax; |p*scale| <~ 7.
// ---------------------------------------------------------------------------
__global__ void agg_kernel(float* __restrict__ out, int N) {
    const int node = (blockIdx.x * blockDim.x + threadIdx.x) >> 5;
    if (node >= N) return;
    const int lane  = threadIdx.x & 31;
    const int hl    = lane & 15;      // position within half-warp
    const int eslot = lane >> 4;      // 0: even edges, 1: odd edges

    const int start = g_off[node];
    const int deg   = g_cnt[node];
    if (lane == 0) g_cnt[node] = 0;   // re-arm histogram for the next replay

    const uint4* fth4 = (const uint4*)g_fth;   // 16 uint4 per row

    // dst row chunk: features 8*hl .. 8*hl+7, from fp16 mirror
    float b[8];
    {
        uint4 braw = fth4[(size_t)node * 16 + hl];
        float2 t0 = __half22float2(*reinterpret_cast<__half2*>(&braw.x));
        float2 t1 = __half22float2(*reinterpret_cast<__half2*>(&braw.y));
        float2 t2 = __half22float2(*reinterpret_cast<__half2*>(&braw.z));
        float2 t3 = __half22float2(*reinterpret_cast<__half2*>(&braw.w));
        b[0] = t0.x; b[1] = t0.y; b[2] = t1.x; b[3] = t1.y;
        b[4] = t2.x; b[5] = t2.y; b[6] = t3.x; b[7] = t3.y;
    }

    float acc[8];
    #pragma unroll
    for (int i = 0; i < 8; i++) acc[i] = 0.0f;
    float s = 0.0f;
    const float scale = 0.17677669529663687f;  // 1/sqrt(32)

    for (int base = 0; base < deg; base += 32) {
        int j = base + lane;
        int sj = (j < deg) ? g_csr_src[start + j] : 0;
        int cnt = min(32, deg - base);

        // prologue: this half-warp's first edge (t=0 -> edge eslot)
        int sn = __shfl_sync(0xffffffffu, sj, min(eslot, 31));
        uint4 raw = fth4[(size_t)sn * 16 + hl];

        #pragma unroll 1
        for (int t = 0; t < cnt; t += 2) {
            uint4 cur = raw;
            bool valid = (t + eslot) < cnt;

            // prefetch next pair's edge (uniform-shape shuffle, clamped idx)
            int nxt = t + 2 + eslot;
            int snn = __shfl_sync(0xffffffffu, sj, min(nxt, 31));
            if (nxt < cnt) raw = fth4[(size_t)snn * 16 + hl];

            // convert 8 halves -> 8 floats, dot with dst chunk
            float2 f0 = __half22float2(*reinterpret_cast<__half2*>(&cur.x));
            float2 f1 = __half22float2(*reinterpret_cast<__half2*>(&cur.y));
            float2 f2 = __half22float2(*reinterpret_cast<__half2*>(&cur.z));
            float2 f3 = __half22float2(*reinterpret_cast<__half2*>(&cur.w));
            float p = f0.x * b[0] + f0.y * b[1] + f1.x * b[2] + f1.y * b[3]
                    + f2.x * b[4] + f2.y * b[5] + f3.x * b[6] + f3.y * b[7];
            // reduce over the 4 lanes of this head quad
            p += __shfl_xor_sync(0xffffffffu, p, 1);
            p += __shfl_xor_sync(0xffffffffu, p, 2);

            float e = valid ? __expf(p * scale) : 0.0f;
            s += e;
            acc[0] += e * f0.x; acc[1] += e * f0.y;
            acc[2] += e * f1.x; acc[3] += e * f1.y;
            acc[4] += e * f2.x; acc[5] += e * f2.y;
            acc[6] += e * f3.x; acc[7] += e * f3.y;
        }
    }

    // merge the two half-warps (same features, disjoint edge subsets)
    #pragma unroll
    for (int i = 0; i < 8; i++)
        acc[i] += __shfl_xor_sync(0xffffffffu, acc[i], 16);
    s += __shfl_xor_sync(0xffffffffu, s, 16);

    float inv = (deg > 0) ? (1.0f / s) : 0.0f;
    float4 v;
    if (eslot == 0) v = make_float4(acc[0] * inv, acc[1] * inv, acc[2] * inv, acc[3] * inv);
    else            v = make_float4(acc[4] * inv, acc[5] * inv, acc[6] * inv, acc[7] * inv);
    *(float4*)&out[(size_t)node * HD + (hl << 3) + (eslot << 2)] = v;
}

// ---------------------------------------------------------------------------
extern "C" void kernel_launch(void* const* d_in, const int* in_sizes, int n_in,
                              void* d_out, int out_size) {
    const float* feat = (const float*)d_in[0];
    const float* W    = (const float*)d_in[1];
    const int*   src  = (const int*)d_in[2];
    const int*   dst  = (const int*)d_in[3];
    float* out = (float*)d_out;

    const int N = in_sizes[0] / IN_FEATS;   // 50000
    const int E = in_sizes[2];              // 800000
    const int nb = (N + SCAN_B - 1) / SCAN_B;

    static cudaStream_t s_gemm = nullptr;
    static cudaEvent_t  ev_fork = nullptr, ev_join = nullptr;
    if (s_gemm == nullptr) {
        cudaStreamCreateWithFlags(&s_gemm, cudaStreamNonBlocking);
        cudaEventCreateWithFlags(&ev_fork, cudaEventDisableTiming);
        cudaEventCreateWithFlags(&ev_join, cudaEventDisableTiming);
    }

    // ---- fork: GEMM branch issued FIRST (R8 order — measured best) ----
    cudaEventRecord(ev_fork, 0);
    cudaStreamWaitEvent(s_gemm, ev_fork, 0);
    gemm_kernel<<<(N + GM - 1) / GM, 256, 0, s_gemm>>>(feat, W, N);
    cudaEventRecord(ev_join, s_gemm);

    // ---- main stream: CSR build branch (depends only on src, dst) ----
    hist_kernel<<<(E + 255) / 256, 256>>>(dst, E);
    scan_phase1<<<nb, SCAN_B>>>(N);
    scan_phase3<<<nb, SCAN_B>>>(N);
    scatter_kernel<<<(E + 255) / 256, 256>>>(src, dst, E);

    // ---- join, then aggregate ----
    cudaStreamWaitEvent(0, ev_join, 0);
    {
        int warps_per_block = 8;  // 256 threads
        int blocks = (N + warps_per_block - 1) / warps_per_block;
        agg_kernel<<<blocks, 256>>>(out, N);
    }
}

// round 17
// speedup vs baseline: 1.4020x; 1.4020x over previous
#include <cuda_runtime.h>
#include <cuda_fp16.h>
#include <cuda_bf16.h>
#include <cstdint>

// Problem constants (fixed by the dataset)
#define N_NODES_MAX 50048
#define N_EDGES_MAX 800000
#define IN_FEATS    128
#define NUM_HEADS   4
#define OUT_FEATS   32
#define HD          (NUM_HEADS * OUT_FEATS)   // 128

#define SCAN_B 1024
#define MAX_BLOCKS ((N_NODES_MAX + SCAN_B - 1) / SCAN_B + 2)

// Scratch (static __device__ arrays; no allocation allowed)
__device__ float   g_ft [N_NODES_MAX * HD];   // projected features fp32 [N,128]
__device__ __half2 g_fth[N_NODES_MAX * 64];   // same rows as half2 (gather mirror)
__device__ int     g_cnt[N_NODES_MAX];        // in-degree histogram
__device__ int     g_off[N_NODES_MAX];        // CSR row starts
__device__ int     g_cur[N_NODES_MAX];        // scatter cursors
__device__ int     g_bsum[MAX_BLOCKS];        // per-block sums for scan
__device__ int     g_csr_src[N_EDGES_MAX];    // src node per CSR slot

// ---------------------------------------------------------------------------
// K1: in-degree histogram — 4 edges per thread (int4 load, 4 pipelined REDs:
// ATOMG latency 318cyc is covered by MLP 4 instead of 1).
// ---------------------------------------------------------------------------
__global__ void hist_kernel(const int* __restrict__ dst, int E) {
    int i4 = (blockIdx.x * blockDim.x + threadIdx.x) << 2;
    if (i4 + 3 < E) {
        int4 d = *(const int4*)&dst[i4];
        atomicAdd(&g_cnt[d.x], 1);
        atomicAdd(&g_cnt[d.y], 1);
        atomicAdd(&g_cnt[d.z], 1);
        atomicAdd(&g_cnt[d.w], 1);
    } else {
        for (int i = i4; i < E; i++) atomicAdd(&g_cnt[dst[i]], 1);
    }
}

// ---------------------------------------------------------------------------
// K2a: per-block sums for the scan
// ---------------------------------------------------------------------------
__global__ void scan_phase1(int N) {
    int i = blockIdx.x * SCAN_B + threadIdx.x;
    int v = (i < N) ? g_cnt[i] : 0;
    #pragma unroll
    for (int o = 16; o > 0; o >>= 1) v += __shfl_xor_sync(0xffffffffu, v, o);
    __shared__ int wsum[32];
    int lane = threadIdx.x & 31, w = threadIdx.x >> 5;
    if (lane == 0) wsum[w] = v;
    __syncthreads();
    if (w == 0) {
        int x = wsum[lane];
        #pragma unroll
        for (int o = 16; o > 0; o >>= 1) x += __shfl_xor_sync(0xffffffffu, x, o);
        if (lane == 0) g_bsum[blockIdx.x] = x;
    }
}

// ---------------------------------------------------------------------------
// K2b: per-block scan with inter-block base folded in (warp 0 sums g_bsum).
// ---------------------------------------------------------------------------
__global__ void scan_phase3(int N) {
    __shared__ int base_off;
    int lane = threadIdx.x & 31, w = threadIdx.x >> 5;
    if (threadIdx.x < 32) {
        int acc = 0;
        for (int j = lane; j < (int)blockIdx.x; j += 32) acc += g_bsum[j];
        #pragma unroll
        for (int o = 16; o > 0; o >>= 1) acc += __shfl_xor_sync(0xffffffffu, acc, o);
        if (lane == 0) base_off = acc;
    }
    int i = blockIdx.x * SCAN_B + threadIdx.x;
    int v = (i < N) ? g_cnt[i] : 0;
    int x = v;
    #pragma unroll
    for (int o = 1; o < 32; o <<= 1) {
        int y = __shfl_up_sync(0xffffffffu, x, o);
        if (lane >= o) x += y;
    }
    __shared__ int woff[32];
    if (lane == 31) woff[w] = x;
    __syncthreads();
    if (w == 0) {
        int y = woff[lane];
        int z = y;
        #pragma unroll
        for (int o = 1; o < 32; o <<= 1) {
            int t2 = __shfl_up_sync(0xffffffffu, z, o);
            if (lane >= o) z += t2;
        }
        woff[lane] = z - y;
    }
    __syncthreads();
    int excl = (x - v) + woff[w] + base_off;
    if (i < N) { g_off[i] = excl; g_cur[i] = excl; }
}

// ---------------------------------------------------------------------------
// K3: scatter src ids into CSR slots — 4 edges per thread (2x int4 loads,
// 4 independent atomicAdds in flight -> ATOMG latency amortized 4x).
// ---------------------------------------------------------------------------
__global__ void scatter_kernel(const int* __restrict__ src,
                               const int* __restrict__ dst, int E) {
    int i4 = (blockIdx.x * blockDim.x + threadIdx.x) << 2;
    if (i4 + 3 < E) {
        int4 s = *(const int4*)&src[i4];
        int4 d = *(const int4*)&dst[i4];
        int p0 = atomicAdd(&g_cur[d.x], 1);
        int p1 = atomicAdd(&g_cur[d.y], 1);
        int p2 = atomicAdd(&g_cur[d.z], 1);
        int p3 = atomicAdd(&g_cur[d.w], 1);
        g_csr_src[p0] = s.x;
        g_csr_src[p1] = s.y;
        g_csr_src[p2] = s.z;
        g_csr_src[p3] = s.w;
    } else {
        for (int i = i4; i < E; i++) {
            int pos = atomicAdd(&g_cur[dst[i]], 1);
            g_csr_src[pos] = src[i];
        }
    }
}

// ---------------------------------------------------------------------------
// K4: projection GEMM — R8/R14 exact shape (measured best; frozen).
// 128x128 tile, BK=16, 256 threads, occ 2, 8x8 microtile as f32x2 pairs.
// Epilogue: fp32 rows + fp16 mirror rows (R14-exact).
// ---------------------------------------------------------------------------
#define GM 128
#define GK 16
__global__ void __launch_bounds__(256, 2)
gemm_kernel(const float* __restrict__ feat,
            const float* __restrict__ W,
            int N) {
    __shared__ float As[GK][GM];    // feat tile, transposed: As[k][r]   8KB
    __shared__ float Bs[GK][HD];    // W tile, transposed:    Bs[k][o]   8KB

    const int tid = threadIdx.x;           // 0..255
    const int tx  = tid & 15;              // col group: cols tx*8..tx*8+7
    const int ty  = tid >> 4;              // row group: rows ty*8..ty*8+7
    const int row0 = blockIdx.x * GM;

    const int rA0 = (tid + 0)   >> 2, kq0 = (tid + 0)   & 3;
    const int rA1 = (tid + 256) >> 2, kq1 = (tid + 256) & 3;

    unsigned long long acc[8][4];   // 8 rows x 4 f32x2 pairs (= 8 cols)
    #pragma unroll
    for (int i = 0; i < 8; i++)
        #pragma unroll
        for (int j = 0; j < 4; j++) acc[i][j] = 0ULL;

    float4 fa0, fa1, fw0, fw1;
    {
        fa0 = make_float4(0.f, 0.f, 0.f, 0.f);
        fa1 = fa0;
        if (row0 + rA0 < N) fa0 = *(const float4*)&feat[(size_t)(row0 + rA0) * IN_FEATS + (kq0 << 2)];
        if (row0 + rA1 < N) fa1 = *(const float4*)&feat[(size_t)(row0 + rA1) * IN_FEATS + (kq1 << 2)];
        fw0 = *(const float4*)&W[(size_t)rA0 * IN_FEATS + (kq0 << 2)];
        fw1 = *(const float4*)&W[(size_t)rA1 * IN_FEATS + (kq1 << 2)];
    }

    #pragma unroll 1
    for (int kb = 0; kb < IN_FEATS / GK; kb++) {
        As[(kq0 << 2) + 0][rA0] = fa0.x; As[(kq0 << 2) + 1][rA0] = fa0.y;
        As[(kq0 << 2) + 2][rA0] = fa0.z; As[(kq0 << 2) + 3][rA0] = fa0.w;
        As[(kq1 << 2) + 0][rA1] = fa1.x; As[(kq1 << 2) + 1][rA1] = fa1.y;
        As[(kq1 << 2) + 2][rA1] = fa1.z; As[(kq1 << 2) + 3][rA1] = fa1.w;
        Bs[(kq0 << 2) + 0][rA0] = fw0.x; Bs[(kq0 << 2) + 1][rA0] = fw0.y;
        Bs[(kq0 << 2) + 2][rA0] = fw0.z; Bs[(kq0 << 2) + 3][rA0] = fw0.w;
        Bs[(kq1 << 2) + 0][rA1] = fw1.x; Bs[(kq1 << 2) + 1][rA1] = fw1.y;
        Bs[(kq1 << 2) + 2][rA1] = fw1.z; Bs[(kq1 << 2) + 3][rA1] = fw1.w;
        __syncthreads();

        if (kb + 1 < IN_FEATS / GK) {
            int kc = (kb + 1) * GK;
            fa0 = make_float4(0.f, 0.f, 0.f, 0.f);
            fa1 = fa0;
            if (row0 + rA0 < N) fa0 = *(const float4*)&feat[(size_t)(row0 + rA0) * IN_FEATS + kc + (kq0 << 2)];
            if (row0 + rA1 < N) fa1 = *(const float4*)&feat[(size_t)(row0 + rA1) * IN_FEATS + kc + (kq1 << 2)];
            fw0 = *(const float4*)&W[(size_t)rA0 * IN_FEATS + kc + (kq0 << 2)];
            fw1 = *(const float4*)&W[(size_t)rA1 * IN_FEATS + kc + (kq1 << 2)];
        }

        #pragma unroll
        for (int k = 0; k < GK; k++) {
            float4 a0 = *(const float4*)&As[k][(ty << 3) + 0];
            float4 a1 = *(const float4*)&As[k][(ty << 3) + 4];
            float4 b0 = *(const float4*)&Bs[k][(tx << 3) + 0];
            float4 b1 = *(const float4*)&Bs[k][(tx << 3) + 4];
            unsigned long long bp[4];
            asm("mov.b64 %0, {%1, %2};" : "=l"(bp[0]) : "f"(b0.x), "f"(b0.y));
            asm("mov.b64 %0, {%1, %2};" : "=l"(bp[1]) : "f"(b0.z), "f"(b0.w));
            asm("mov.b64 %0, {%1, %2};" : "=l"(bp[2]) : "f"(b1.x), "f"(b1.y));
            asm("mov.b64 %0, {%1, %2};" : "=l"(bp[3]) : "f"(b1.z), "f"(b1.w));
            float av[8] = {a0.x, a0.y, a0.z, a0.w, a1.x, a1.y, a1.z, a1.w};
            #pragma unroll
            for (int i = 0; i < 8; i++) {
                unsigned long long ap;
                asm("mov.b64 %0, {%1, %1};" : "=l"(ap) : "f"(av[i]));
                #pragma unroll
                for (int jp = 0; jp < 4; jp++)
                    asm("fma.rn.f32x2 %0, %1, %2, %0;"
                        : "+l"(acc[i][jp]) : "l"(ap), "l"(bp[jp]));
            }
        }
        __syncthreads();
    }

    #pragma unroll
    for (int i = 0; i < 8; i++) {
        int r = row0 + (ty << 3) + i;
        if (r < N) {
            unsigned long long* d =
                (unsigned long long*)&g_ft[(size_t)r * HD + (tx << 3)];
            ulonglong2 v0; v0.x = acc[i][0]; v0.y = acc[i][1];
            ulonglong2 v1; v1.x = acc[i][2]; v1.y = acc[i][3];
            *(ulonglong2*)(d + 0) = v0;
            *(ulonglong2*)(d + 2) = v1;

            __half2 hh[4];
            #pragma unroll
            for (int jp = 0; jp < 4; jp++) {
                float2 f = *reinterpret_cast<float2*>(&acc[i][jp]);
                hh[jp] = __floats2half2_rn(f.x, f.y);
            }
            *(uint2*)&g_fth[(size_t)r * 64 + (tx << 2) + 0] = *(uint2*)&hh[0];
            *(uint2*)&g_fth[(size_t)r * 64 + (tx << 2) + 2] = *(uint2*)&hh[2];
        }
    }
}

// ---------------------------------------------------------------------------
// K5: atomic-free aggregation — R14 exact (measured best; frozen).
// Half-warp per edge: lanes 0-15 take edge t, lanes 16-31 edge t+1; lane
// holds 8 features (one uint4 of the 256B fp16 row); head reduction = 2
// shuffles; halves merged once per node via xor-16. dst row from fp32 g_ft.
// Max-subtraction skipped: mathematically identical softmax; |p*scale| <~ 7.
// ---------------------------------------------------------------------------
__global__ void agg_kernel(float* __restrict__ out, int N) {
    const int node = (blockIdx.x * blockDim.x + threadIdx.x) >> 5;
    if (node >= N) return;
    const int lane  = threadIdx.x & 31;
    const int hl    = lane & 15;      // position within half-warp
    const int eslot = lane >> 4;      // 0: even edges, 1: odd edges

    const int start = g_off[node];
    const int deg   = g_cnt[node];

    // dst row chunk: features 8*hl .. 8*hl+7, fp32
    float b[8];
    {
        float4 b0 = *(const float4*)&g_ft[(size_t)node * HD + (hl << 3) + 0];
        float4 b1 = *(const float4*)&g_ft[(size_t)node * HD + (hl << 3) + 4];
        b[0] = b0.x; b[1] = b0.y; b[2] = b0.z; b[3] = b0.w;
        b[4] = b1.x; b[5] = b1.y; b[6] = b1.z; b[7] = b1.w;
    }

    float acc[8];
    #pragma unroll
    for (int i = 0; i < 8; i++) acc[i] = 0.0f;
    float s = 0.0f;
    const float scale = 0.17677669529663687f;  // 1/sqrt(32)

    const uint4* fth4 = (const uint4*)g_fth;   // 16 uint4 per row

    for (int base = 0; base < deg; base += 32) {
        int j = base + lane;
        int sj = (j < deg) ? g_csr_src[start + j] : 0;
        int cnt = min(32, deg - base);

        // prologue: this half-warp's first edge (t=0 -> edge eslot)
        int my = eslot;
        int sn = __shfl_sync(0xffffffffu, sj, min(my, 31));
        uint4 raw = fth4[(size_t)sn * 16 + hl];

        #pragma unroll 1
        for (int t = 0; t < cnt; t += 2) {
            uint4 cur = raw;
            bool valid = (t + eslot) < cnt;

            // prefetch next pair's edge (uniform-shape shuffle, clamped idx)
            int nxt = t + 2 + eslot;
            int snn = __shfl_sync(0xffffffffu, sj, min(nxt, 31));
            if (nxt < cnt) raw = fth4[(size_t)snn * 16 + hl];

            // convert 8 halves -> 8 floats, dot with dst chunk
            float2 f0 = __half22float2(*reinterpret_cast<__half2*>(&cur.x));
            float2 f1 = __half22float2(*reinterpret_cast<__half2*>(&cur.y));
            float2 f2 = __half22float2(*reinterpret_cast<__half2*>(&cur.z));
            float2 f3 = __half22float2(*reinterpret_cast<__half2*>(&cur.w));
            float p = f0.x * b[0] + f0.y * b[1] + f1.x * b[2] + f1.y * b[3]
                    + f2.x * b[4] + f2.y * b[5] + f3.x * b[6] + f3.y * b[7];
            // reduce over the 4 lanes of this head quad
            p += __shfl_xor_sync(0xffffffffu, p, 1);
            p += __shfl_xor_sync(0xffffffffu, p, 2);

            float e = valid ? __expf(p * scale) : 0.0f;
            s += e;
            acc[0] += e * f0.x; acc[1] += e * f0.y;
            acc[2] += e * f1.x; acc[3] += e * f1.y;
            acc[4] += e * f2.x; acc[5] += e * f2.y;
            acc[6] += e * f3.x; acc[7] += e * f3.y;
        }
    }

    // merge the two half-warps (same features, disjoint edge subsets)
    #pragma unroll
    for (int i = 0; i < 8; i++)
        acc[i] += __shfl_xor_sync(0xffffffffu, acc[i], 16);
    s += __shfl_xor_sync(0xffffffffu, s, 16);

    float inv = (deg > 0) ? (1.0f / s) : 0.0f;
    float4 v;
    if (eslot == 0) v = make_float4(acc[0] * inv, acc[1] * inv, acc[2] * inv, acc[3] * inv);
    else            v = make_float4(acc[4] * inv, acc[5] * inv, acc[6] * inv, acc[7] * inv);
    *(float4*)&out[(size_t)node * HD + (hl << 3) + (eslot << 2)] = v;
}

// ---------------------------------------------------------------------------
extern "C" void kernel_launch(void* const* d_in, const int* in_sizes, int n_in,
                              void* d_out, int out_size) {
    const float* feat = (const float*)d_in[0];
    const float* W    = (const float*)d_in[1];
    const int*   src  = (const int*)d_in[2];
    const int*   dst  = (const int*)d_in[3];
    float* out = (float*)d_out;

    const int N = in_sizes[0] / IN_FEATS;   // 50000
    const int E = in_sizes[2];              // 800000
    const int nb = (N + SCAN_B - 1) / SCAN_B;

    static cudaStream_t s_gemm = nullptr;
    static cudaEvent_t  ev_fork = nullptr, ev_join = nullptr;
    static int* cnt_ptr = nullptr;
    if (s_gemm == nullptr) {
        cudaStreamCreateWithFlags(&s_gemm, cudaStreamNonBlocking);
        cudaEventCreateWithFlags(&ev_fork, cudaEventDisableTiming);
        cudaEventCreateWithFlags(&ev_join, cudaEventDisableTiming);
        cudaGetSymbolAddress((void**)&cnt_ptr, g_cnt);
    }

    // ---- fork: GEMM branch issued FIRST (R8/R14 order — measured best) ----
    cudaEventRecord(ev_fork, 0);
    cudaStreamWaitEvent(s_gemm, ev_fork, 0);
    gemm_kernel<<<(N + GM - 1) / GM, 256, 0, s_gemm>>>(feat, W, N);
    cudaEventRecord(ev_join, s_gemm);

    // ---- main stream: CSR build branch (depends only on src, dst) ----
    cudaMemsetAsync(cnt_ptr, 0, (size_t)N * sizeof(int));
    {
        int nthreads = (E + 3) / 4;
        hist_kernel<<<(nthreads + 255) / 256, 256>>>(dst, E);
    }
    scan_phase1<<<nb, SCAN_B>>>(N);
    scan_phase3<<<nb, SCAN_B>>>(N);
    {
        int nthreads = (E + 3) / 4;
        scatter_kernel<<<(nthreads + 255) / 256, 256>>>(src, dst, E);
    }

    // ---- join, then aggregate ----
    cudaStreamWaitEvent(0, ev_join, 0);
    {
        int warps_per_block = 8;  // 256 threads
        int blocks = (N + warps_per_block - 1) / warps_per_block;
        agg_kernel<<<blocks, 256>>>(out, N);
    }
}